// round 8
// baseline (speedup 1.0000x reference)
#include <cuda_runtime.h>
#include <math.h>

#define BGRAPH 128
#define NPG    512
#define NNODES (BGRAPH*NPG)
#define EPG    (NPG*16)
#define NEDGE  (NNODES*16)
#define NT     1024
#define NW     32

typedef unsigned long long ull;

// cross-kernel scratch
__device__ float g_u[2][3][BGRAPH*640];
__device__ float g_part[BGRAPH][96];

// SMEM byte offsets for k_fused
#define OFF_XBUF 0          // 512*64 f = 131072
#define OFF_YBUF 131072     // 512*32 f =  65536
#define OFF_CSR  196608     // ushort[9728] = 19456
#define OFF_OFFS 216064     // ushort[513] -> 1032
#define OFF_INV  217096     // float[512] = 2048
#define OFF_PAD  219144     // uchar[512] = 512
#define OFF_SCR  219656     // int[1040] = 4160
#define OFF_WT   223816     // float[32*66] = 8448 (transposed weight tile)
#define SMEM_BYTES 232264   // <= 232448 cap

// ---- f32x2 helpers ----
__device__ __forceinline__ void FMA2(ull& d, ull a, ull b) {
    asm("fma.rn.f32x2 %0, %1, %2, %0;" : "+l"(d) : "l"(a), "l"(b));
}
__device__ __forceinline__ void ADD2(ull& d, ull a) {
    asm("add.rn.f32x2 %0, %0, %1;" : "+l"(d) : "l"(a));
}
__device__ __forceinline__ ull PK2(float x, float y) {
    ull r; asm("mov.b64 %0, {%1, %2};" : "=l"(r) : "f"(x), "f"(y)); return r;
}
__device__ __forceinline__ float2 UP2(ull v) {
    float2 r; asm("mov.b64 {%0, %1}, %2;" : "=f"(r.x), "=f"(r.y) : "l"(v)); return r;
}

// ---- transpose weight tile into SMEM: wt[c*66 + k] = W[k*FO + cbase + c] ----
__device__ __forceinline__ void transp(const float* __restrict__ W, int FO, int cbase,
                                       int ncols, int FI, float* __restrict__ wt, int tid)
{
    for (int t = tid; t < ncols * FI; t += NT) {
        int k = t / ncols, c = t - k * ncols;
        wt[c * 66 + k] = __ldg(W + k * FO + cbase + c);
    }
}

// ---- XW half-tile: cols [cbase, cbase+32) (or 16), rows [row0, row0+nrows) ----
// Y[n, cbase+cl] = (sum_k X[n,k] Wt[cl,k]) * inv[n]
template<int FI, int FOS, int R>
__device__ __forceinline__ void xw_half(
    const float* __restrict__ Xs, int xstride, int row0, int nrows,
    float* __restrict__ Ys, int cbase, const float* __restrict__ wt,
    const float* __restrict__ invsh, int warp, int cl)
{
    for (int grp = warp; grp < nrows / R; grp += NW) {
        int r0 = grp * R;
        ull acc[R];
        #pragma unroll
        for (int r = 0; r < R; r++) acc[r] = 0ull;
        #pragma unroll 4
        for (int k = 0; k < FI; k += 4) {
            ull w01 = *(const ull*)(wt + cl * 66 + k);
            ull w23 = *(const ull*)(wt + cl * 66 + k + 2);
            #pragma unroll
            for (int r = 0; r < R; r++) {
                ulonglong2 xv = *(const ulonglong2*)(Xs + (r0 + r) * xstride + k);
                FMA2(acc[r], xv.x, w01);
                FMA2(acc[r], xv.y, w23);
            }
        }
        #pragma unroll
        for (int r = 0; r < R; r++) {
            int n = row0 + r0 + r;
            float2 v = UP2(acc[r]);
            Ys[n * FOS + cbase + cl] = (v.x + v.y) * invsh[n];
        }
    }
}

// ---- aggregation FO=32, scalar (1 ch/lane), direct write ----
__device__ __forceinline__ void agg32(
    const float* __restrict__ Ys, float* __restrict__ Out,
    const ushort4* __restrict__ csr4, const unsigned short* __restrict__ offsh,
    const float* __restrict__ invsh, const unsigned char* __restrict__ padsh,
    const float* __restrict__ bias, int warp, int lane)
{
    const float b0 = __ldg(bias + lane);
    for (int n = warp; n < NPG; n += NW) {
        int q0 = offsh[n] >> 2, q1 = offsh[n + 1] >> 2;
        float a0 = 0.f;
        for (int q = q0; q < q1; q++) {
            ushort4 ix = csr4[q];
            a0 += Ys[ix.x * 32 + lane];
            a0 += Ys[ix.y * 32 + lane];
            a0 += Ys[ix.z * 32 + lane];
            a0 += Ys[ix.w * 32 + lane];
        }
        float corr = 1.f - (float)padsh[n];
        a0 = fmaf(corr, Ys[n * 32 + lane], a0);
        Out[n * 32 + lane] = fmaxf(a0 * invsh[n] + b0, 0.f);
    }
}

// ---- resize-tap projection ----
template<int FO>
__device__ __forceinline__ void taps(const float* __restrict__ Hs, int stride,
                                     float* __restrict__ uout, int tid)
{
    for (int t = tid; t < 10 * FO; t += NT) {
        int p = t / FO, d = t % FO;
        float c = (p + 0.5f) * 51.2f - 0.5f;
        int i0 = (int)floorf(c);
        float w = c - (float)i0;
        uout[p * 64 + d] = Hs[i0 * stride + d] * (1.f - w) + Hs[(i0 + 1) * stride + d] * w;
    }
}

// ---------------- fused per-(graph,side) kernel ----------------
__global__ void __launch_bounds__(NT, 1)
k_fused(const float* __restrict__ x0, const float* __restrict__ x1,
        const float* __restrict__ W0, const float* __restrict__ b0,
        const float* __restrict__ W1, const float* __restrict__ b1,
        const float* __restrict__ W2, const float* __restrict__ b2,
        const int* __restrict__ ei, const int* __restrict__ ej)
{
    extern __shared__ char smraw[];
    float*          xbuf  = (float*)(smraw + OFF_XBUF);
    float*          ybuf  = (float*)(smraw + OFF_YBUF);
    unsigned short* csr   = (unsigned short*)(smraw + OFF_CSR);
    const ushort4*  csr4  = (const ushort4*)csr;
    unsigned short* offsh = (unsigned short*)(smraw + OFF_OFFS);
    float*          invsh = (float*)(smraw + OFF_INV);
    unsigned char*  padsh = (unsigned char*)(smraw + OFF_PAD);
    int*            cnt   = (int*)(smraw + OFF_SCR);   // [512]
    int*            cur   = cnt + 512;                 // [512]
    int*            wtot  = cnt + 1024;                // [16]
    float*          wt    = (float*)(smraw + OFF_WT);  // [32*66]

    const int side = blockIdx.y, g = blockIdx.x;
    const int tid = threadIdx.x, warp = tid >> 5, lane = tid & 31;
    const int* E    = side ? ej : ei;
    const int* esrc = E + g * EPG;
    const int* edst = E + NEDGE + g * EPG;
    const float* Xg = (side ? x1 : x0) + (size_t)g * NPG * 64;

    // ---- count pass: cache src/dst in ybuf (ushort), count degrees ----
    unsigned short* srcc = (unsigned short*)ybuf;   // [8192]
    unsigned short* dstc = srcc + EPG;              // [8192]
    if (tid < 512) cnt[tid] = 0;
    __syncthreads();
    for (int e = tid; e < EPG; e += NT) {
        int sv = esrc[e] & (NPG - 1), dv = edst[e] & (NPG - 1);
        srcc[e] = (unsigned short)sv;
        dstc[e] = (unsigned short)dv;
        atomicAdd(&cnt[dv], 1);
    }
    __syncthreads();

    // ---- scan of padded degrees ----
    int deg = 0, pc = 0, s_incl = 0, off = 0;
    if (tid < 512) {
        deg = cnt[tid];
        pc  = (deg + 3) & ~3;
        s_incl = pc;
        #pragma unroll
        for (int d = 1; d < 32; d <<= 1) {
            int v = __shfl_up_sync(0xffffffffu, s_incl, d);
            if (lane >= d) s_incl += v;
        }
        if (lane == 31) wtot[warp] = s_incl;
    }
    __syncthreads();
    if (tid < 16) {
        int t = wtot[tid];
        #pragma unroll
        for (int d = 1; d < 16; d <<= 1) {
            int v = __shfl_up_sync(0x0000ffffu, t, d);
            if (tid >= d) t += v;
        }
        wtot[tid] = t;
    }
    __syncthreads();
    if (tid < 512) {
        int base = warp ? wtot[warp - 1] : 0;
        off = base + s_incl - pc;
        offsh[tid] = (unsigned short)off;
        if (tid == 511) offsh[512] = (unsigned short)(off + pc);
        invsh[tid] = rsqrtf((float)deg + 1.0f);
        padsh[tid] = (unsigned char)(pc - deg);
        cur[tid] = off;
    }
    __syncthreads();

    // ---- fill pass: SMEM only ----
    for (int e = tid; e < EPG; e += NT) {
        int dv = dstc[e];
        int p = atomicAdd(&cur[dv], 1);
        csr[p] = srcc[e];
    }
    if (tid < 512)
        for (int t = deg; t < pc; t++) csr[off + t] = (unsigned short)tid;
    __syncthreads();

    // ---- layer 0 XW: two 256-row X chunks, two 32-col weight halves ----
    for (int ch = 0; ch < 2; ch++) {
        const float4* src = (const float4*)(Xg + (size_t)ch * 256 * 64);
        float4* dst = (float4*)ybuf;
        for (int i = tid; i < 4096; i += NT) dst[i] = src[i];
        transp(W0, 64, 0, 32, 64, wt, tid);
        __syncthreads();
        xw_half<64, 64, 8>(ybuf, 64, ch * 256, 256, xbuf, 0, wt, invsh, warp, lane);
        __syncthreads();
        transp(W0, 64, 32, 32, 64, wt, tid);
        __syncthreads();
        xw_half<64, 64, 8>(ybuf, 64, ch * 256, 256, xbuf, 32, wt, invsh, warp, lane);
        __syncthreads();
    }

    // ---- agg0 (f32x2, channel pairs 2l/2l+1), stage in regs, write back ----
    {
        ull h[16];
        const float2 bb = *(const float2*)(b0 + 2 * lane);
        const int l2 = 2 * lane;
        #pragma unroll
        for (int it = 0; it < 16; it++) {
            int n = warp + it * NW;
            int q0 = offsh[n] >> 2, q1 = offsh[n + 1] >> 2;
            ull a = 0ull;
            for (int q = q0; q < q1; q++) {
                ushort4 ix = csr4[q];
                ADD2(a, *(const ull*)(xbuf + ix.x * 64 + l2));
                ADD2(a, *(const ull*)(xbuf + ix.y * 64 + l2));
                ADD2(a, *(const ull*)(xbuf + ix.z * 64 + l2));
                ADD2(a, *(const ull*)(xbuf + ix.w * 64 + l2));
            }
            float corr = 1.f - (float)padsh[n];
            FMA2(a, PK2(corr, corr), *(const ull*)(xbuf + n * 64 + l2));
            float2 v = UP2(a);
            float inv = invsh[n];
            v.x = fmaxf(v.x * inv + bb.x, 0.f);
            v.y = fmaxf(v.y * inv + bb.y, 0.f);
            h[it] = PK2(v.x, v.y);
        }
        __syncthreads();
        #pragma unroll
        for (int it = 0; it < 16; it++) {
            int n = warp + it * NW;
            *(ull*)(xbuf + n * 64 + l2) = h[it];
        }
        __syncthreads();
    }

    // ---- taps0 + transpose W1, then XW1 ----
    taps<64>(xbuf, 64, &g_u[side][0][g * 640], tid);
    transp(W1, 32, 0, 32, 64, wt, tid);
    __syncthreads();
    xw_half<64, 32, 8>(xbuf, 64, 0, NPG, ybuf, 0, wt, invsh, warp, lane);
    __syncthreads();

    // ---- agg1: ybuf -> xbuf ----
    agg32(ybuf, xbuf, csr4, offsh, invsh, padsh, b1, warp, lane);
    __syncthreads();

    // ---- taps1 + transpose W2, then XW2 ----
    taps<32>(xbuf, 32, &g_u[side][1][g * 640], tid);
    transp(W2, 16, 0, 16, 32, wt, tid);
    __syncthreads();
    xw_half<32, 16, 8>(xbuf, 32, 0, NPG, ybuf, 0, wt, invsh, warp, lane & 15);
    __syncthreads();

    // ---- fused agg2 + taps2: only the 20 tap rows ----
    float* tmp = (float*)cnt;
    if (warp < 20) {
        int p = warp >> 1;
        float c = (p + 0.5f) * 51.2f - 0.5f;
        int i0 = (int)floorf(c);
        int r = i0 + (warp & 1);
        int c0 = lane & 15;
        int q0 = offsh[r] >> 2, q1 = offsh[r + 1] >> 2;
        float a = 0.f;
        for (int q = q0; q < q1; q++) {
            ushort4 ix = csr4[q];
            a += ybuf[ix.x * 16 + c0];
            a += ybuf[ix.y * 16 + c0];
            a += ybuf[ix.z * 16 + c0];
            a += ybuf[ix.w * 16 + c0];
        }
        a = fmaf(1.f - (float)padsh[r], ybuf[r * 16 + c0], a);
        tmp[warp * 16 + c0] = a * invsh[r] + __ldg(b2 + c0);
    }
    __syncthreads();
    if (tid < 160) {
        int p = tid >> 4, d = tid & 15;
        float c = (p + 0.5f) * 51.2f - 0.5f;
        int i0 = (int)floorf(c);
        float w = c - (float)i0;
        g_u[side][2][g * 640 + p * 64 + d] =
            tmp[(2 * p) * 16 + d] * (1.f - w) + tmp[(2 * p + 1) * 16 + d] * w;
    }
}

// ---------------- headA: per (graph,layer): sim + conv + partial MLP0 ----------------
__global__ void __launch_bounds__(256)
k_headA(const float* __restrict__ cw0, const float* __restrict__ cb0,
        const float* __restrict__ cw1, const float* __restrict__ cb1,
        const float* __restrict__ cw2, const float* __restrict__ cb2,
        const float* __restrict__ mw0)
{
    int b = blockIdx.x, l = blockIdx.y;
    int tid = threadIdx.x, warp = tid >> 5, lane = tid & 31;
    __shared__ float ui[640], uj[640];
    __shared__ float sim[100];
    __shared__ float feat[800];
    __shared__ float cwsm[72], cbsm[8];
    __shared__ float red[8][32];

    for (int t = tid; t < 640; t += 256) {
        ui[t] = g_u[0][l][b*640 + t];
        uj[t] = g_u[1][l][b*640 + t];
    }
    const float* cw = (l==0) ? cw0 : (l==1) ? cw1 : cw2;
    const float* cb = (l==0) ? cb0 : (l==1) ? cb1 : cb2;
    if (tid < 72) cwsm[tid] = __ldg(cw + tid);
    if (tid >= 128 && tid < 136) cbsm[tid-128] = __ldg(cb + tid - 128);
    __syncthreads();

    const int fo = 64 >> l;
    for (int ent = warp; ent < 100; ent += 8) {
        int p = ent / 10, q = ent % 10;
        float s = 0.f;
        for (int d = lane; d < fo; d += 32)
            s = fmaf(ui[p*64 + d], uj[q*64 + d], s);
        #pragma unroll
        for (int o = 16; o; o >>= 1) s += __shfl_xor_sync(0xffffffffu, s, o);
        if (lane == 0) sim[ent] = s;
    }
    __syncthreads();

    for (int t = tid; t < 800; t += 256) {
        int ch = t / 100, rc = t % 100, r = rc / 10, c = rc % 10;
        float acc = cbsm[ch];
        #pragma unroll
        for (int dr = 0; dr < 3; dr++)
            #pragma unroll
            for (int dc = 0; dc < 3; dc++) {
                int rr = r + dr - 1, cc = c + dc - 1;
                if (rr >= 0 && rr < 10 && cc >= 0 && cc < 10)
                    acc = fmaf(cwsm[ch*9 + dr*3 + dc], sim[rr*10 + cc], acc);
            }
        feat[t] = fmaxf(acc, 0.f);
    }
    __syncthreads();

    {
        int o = lane, part = warp;
        const float* w0 = mw0 + (size_t)l * 800 * 32;
        float acc = 0.f;
        #pragma unroll 5
        for (int k = part; k < 800; k += 8)
            acc = fmaf(feat[k], __ldg(w0 + k*32 + o), acc);
        red[part][o] = acc;
    }
    __syncthreads();
    if (tid < 32) {
        float s = 0.f;
        #pragma unroll
        for (int p = 0; p < 8; p++) s += red[p][tid];
        g_part[b][l*32 + tid] = s;
    }
}

// ---------------- headB: warp per graph: sum partials + MLP tail + sigmoid ----------------
__global__ void __launch_bounds__(1024)
k_headB(const float* __restrict__ mb0,
        const float* __restrict__ mw1, const float* __restrict__ mb1,
        const float* __restrict__ mw2, const float* __restrict__ mb2,
        const float* __restrict__ mw3, const float* __restrict__ mb3,
        const float* __restrict__ mw4, const float* __restrict__ mb4,
        const float* __restrict__ sw,  const float* __restrict__ sb,
        float* __restrict__ out)
{
    int b = (blockIdx.x * 1024 + threadIdx.x) >> 5;
    int lane = threadIdx.x & 31;
    if (b >= BGRAPH) return;

    float s = __ldg(mb0 + lane) + g_part[b][lane] + g_part[b][32 + lane] + g_part[b][64 + lane];
    float a0 = fmaxf(s, 0.f);

    float a1 = (lane < 16) ? __ldg(mb1 + lane) : 0.f;
    #pragma unroll
    for (int k = 0; k < 32; k++) {
        float v = __shfl_sync(0xffffffffu, a0, k);
        if (lane < 16) a1 = fmaf(v, __ldg(mw1 + k*16 + lane), a1);
    }
    a1 = fmaxf(a1, 0.f);

    float a2 = (lane < 8) ? __ldg(mb2 + lane) : 0.f;
    #pragma unroll
    for (int k = 0; k < 16; k++) {
        float v = __shfl_sync(0xffffffffu, a1, k);
        if (lane < 8) a2 = fmaf(v, __ldg(mw2 + k*8 + lane), a2);
    }
    a2 = fmaxf(a2, 0.f);

    float a3 = (lane < 4) ? __ldg(mb3 + lane) : 0.f;
    #pragma unroll
    for (int k = 0; k < 8; k++) {
        float v = __shfl_sync(0xffffffffu, a2, k);
        if (lane < 4) a3 = fmaf(v, __ldg(mw3 + k*4 + lane), a3);
    }
    a3 = fmaxf(a3, 0.f);

    float v0 = __shfl_sync(0xffffffffu, a3, 0);
    float v1 = __shfl_sync(0xffffffffu, a3, 1);
    float v2 = __shfl_sync(0xffffffffu, a3, 2);
    float v3 = __shfl_sync(0xffffffffu, a3, 3);
    if (lane == 0) {
        float s4 = __ldg(mb4);
        s4 = fmaf(v0, __ldg(mw4 + 0), s4);
        s4 = fmaf(v1, __ldg(mw4 + 1), s4);
        s4 = fmaf(v2, __ldg(mw4 + 2), s4);
        s4 = fmaf(v3, __ldg(mw4 + 3), s4);
        float f = fmaxf(s4, 0.f);
        float sc = f * __ldg(sw) + __ldg(sb);
        out[b] = 1.f / (1.f + expf(-sc));
    }
}

// ---------------- launch ----------------
extern "C" void kernel_launch(void* const* d_in, const int* in_sizes, int n_in,
                              void* d_out, int out_size) {
    const float* x_i = (const float*)d_in[0];
    const float* x_j = (const float*)d_in[1];
    const float* gw0 = (const float*)d_in[2];  const float* gb0 = (const float*)d_in[3];
    const float* gw1 = (const float*)d_in[4];  const float* gb1 = (const float*)d_in[5];
    const float* gw2 = (const float*)d_in[6];  const float* gb2 = (const float*)d_in[7];
    const float* cw0 = (const float*)d_in[8];  const float* cb0 = (const float*)d_in[9];
    const float* cw1 = (const float*)d_in[10]; const float* cb1 = (const float*)d_in[11];
    const float* cw2 = (const float*)d_in[12]; const float* cb2 = (const float*)d_in[13];
    const float* mw0 = (const float*)d_in[14]; const float* mb0 = (const float*)d_in[15];
    const float* mw1 = (const float*)d_in[16]; const float* mb1 = (const float*)d_in[17];
    const float* mw2 = (const float*)d_in[18]; const float* mb2 = (const float*)d_in[19];
    const float* mw3 = (const float*)d_in[20]; const float* mb3 = (const float*)d_in[21];
    const float* mw4 = (const float*)d_in[22]; const float* mb4 = (const float*)d_in[23];
    const float* sw  = (const float*)d_in[24]; const float* sb  = (const float*)d_in[25];
    const int*   ei  = (const int*)d_in[26];
    const int*   ej  = (const int*)d_in[27];

    cudaFuncSetAttribute(k_fused, cudaFuncAttributeMaxDynamicSharedMemorySize, SMEM_BYTES);

    k_fused<<<dim3(BGRAPH, 2), NT, SMEM_BYTES>>>(x_i, x_j, gw0, gb0, gw1, gb1, gw2, gb2, ei, ej);
    k_headA<<<dim3(BGRAPH, 3), 256>>>(cw0, cb0, cw1, cb1, cw2, cb2, mw0);
    k_headB<<<(BGRAPH*32 + 1023)/1024, 1024>>>(mb0, mw1, mb1, mw2, mb2, mw3, mb3, mw4, mb4,
                                               sw, sb, (float*)d_out);
}